// round 8
// baseline (speedup 1.0000x reference)
#include <cuda_runtime.h>
#include <cuda_bf16.h>
#include <cstdint>

typedef unsigned long long u64;

#define B_SZ   8192
#define NPROD  50
#define DXF    32
#define DZF    20
#define NROWS  (B_SZ * NPROD)       // 409600

// ---------------- scratch (device globals, no allocation) ----------------
__device__ float g_Zj[3 * B_SZ * 16];                    // [KZ][B][16]
__device__ float g_D[3 * B_SZ * 128];                    // [KZ][B][128]
__device__ float g_E[(size_t)3 * 128 * NROWS];           // [KX][128][NROWS] column-major
__device__ float g_scores[9 * NROWS];                    // [pair][B][n]
__device__ __nv_bfloat16 g_Wbf[2][2][128 * 128];         // [layer][hi/lo][n][k]

// ---------------- packed f32x2 helpers (scalar kernels) ----------------
__device__ __forceinline__ u64 pk2(float lo, float hi) {
    u64 r; asm("mov.b64 %0, {%1, %2};" : "=l"(r) : "f"(lo), "f"(hi)); return r;
}
__device__ __forceinline__ void upk2(u64 v, float& lo, float& hi) {
    asm("mov.b64 {%0, %1}, %2;" : "=f"(lo), "=f"(hi) : "l"(v));
}
__device__ __forceinline__ void f2fma(u64& d, u64 a, u64 b) {
    asm("fma.rn.f32x2 %0, %1, %2, %0;" : "+l"(d) : "l"(a), "l"(b));
}
__device__ __forceinline__ float eluf(float x) { return x > 0.f ? x : expm1f(x); }

__device__ __forceinline__ uint32_t smem_u32(const void* p) {
    uint32_t a;
    asm("{ .reg .u64 t; cvta.to.shared.u64 t, %1; cvt.u32.u64 %0, t; }" : "=r"(a) : "l"(p));
    return a;
}

// bf16 split: hi = bf16(v), lo = bf16(v - hi), packed pairs
__device__ __forceinline__ void split2(float v0, float v1, uint32_t& hi, uint32_t& lo) {
    __nv_bfloat162 hp = __floats2bfloat162_rn(v0, v1);
    float2 hf = __bfloat1622float2(hp);
    __nv_bfloat162 lp = __floats2bfloat162_rn(v0 - hf.x, v1 - hf.y);
    hi = *reinterpret_cast<uint32_t*>(&hp);
    lo = *reinterpret_cast<uint32_t*>(&lp);
}

#define LDSM4(r0, r1, r2, r3, addr) \
    asm volatile("ldmatrix.sync.aligned.m8n8.x4.shared.b16 {%0,%1,%2,%3}, [%4];" \
        : "=r"(r0), "=r"(r1), "=r"(r2), "=r"(r3) : "r"(addr))

#define MMA_BF16(c, a0, a1, a2, a3, b0, b1) \
    asm volatile("mma.sync.aligned.m16n8k16.row.col.f32.bf16.bf16.f32 " \
        "{%0,%1,%2,%3}, {%4,%5,%6,%7}, {%8,%9}, {%0,%1,%2,%3};" \
        : "+f"((c)[0]), "+f"((c)[1]), "+f"((c)[2]), "+f"((c)[3]) \
        : "r"(a0), "r"(a1), "r"(a2), "r"(a3), "r"(b0), "r"(b1))

// Dense layer, register input/output, weights in shared. [IN][OUT] row-major.
template<int IN, int OUT, bool ELU>
__device__ __forceinline__ void dense_reg(const float (&in)[IN], const float* wsh, float (&out)[OUT]) {
    u64 acc[OUT / 2];
#pragma unroll
    for (int jj = 0; jj < OUT / 2; jj++) acc[jj] = 0ull;
#pragma unroll
    for (int k = 0; k < IN; k++) {
        u64 xk = pk2(in[k], in[k]);
        const ulonglong2* w = (const ulonglong2*)(wsh + k * OUT);
#pragma unroll
        for (int q = 0; q < OUT / 4; q++) {
            ulonglong2 ww = w[q];
            f2fma(acc[2 * q],     xk, ww.x);
            f2fma(acc[2 * q + 1], xk, ww.y);
        }
    }
#pragma unroll
    for (int jj = 0; jj < OUT / 2; jj++) {
        float lo, hi; upk2(acc[jj], lo, hi);
        out[2 * jj]     = ELU ? eluf(lo) : lo;
        out[2 * jj + 1] = ELU ? eluf(hi) : hi;
    }
}

template<int IN>
__device__ __forceinline__ void dense_half_reg(const float (&in)[IN], const float* wcol, u64 (&acc)[32]) {
#pragma unroll
    for (int q = 0; q < 32; q++) acc[q] = 0ull;
#pragma unroll
    for (int k = 0; k < IN; k++) {
        u64 uk = pk2(in[k], in[k]);
        const ulonglong2* w = (const ulonglong2*)(wcol + k * 128);
#pragma unroll
        for (int q = 0; q < 16; q++) {
            ulonglong2 ww = w[q];
            f2fma(acc[2 * q],     uk, ww.x);
            f2fma(acc[2 * q + 1], uk, ww.y);
        }
    }
}

// ============================================================
// Kernel 1: Z-branch.
// ============================================================
__global__ void __launch_bounds__(128) z_kernel(const float* __restrict__ Zin,
                                                const float* __restrict__ Wz0,
                                                const float* __restrict__ Wz,
                                                const float* __restrict__ Wlz) {
    __shared__ __align__(16) float w0[20 * 64];
    __shared__ __align__(16) float w1[64 * 64];
    __shared__ __align__(16) float w2[64 * 64];
    __shared__ __align__(16) float wl[64 * 16];
    const int j   = blockIdx.x >> 6;
    const int tid = threadIdx.x;
    const int b   = ((blockIdx.x & 63) << 7) + tid;

    {
        const float4* p0 = (const float4*)(Wz0 + j * 1280);
        const float4* p1 = (const float4*)(Wz  + j * 8192);
        const float4* p2 = (const float4*)(Wz  + j * 8192 + 4096);
        const float4* pl = (const float4*)(Wlz + j * 1024);
        for (int t = tid; t < 320;  t += 128) ((float4*)w0)[t] = p0[t];
        for (int t = tid; t < 1024; t += 128) ((float4*)w1)[t] = p1[t];
        for (int t = tid; t < 1024; t += 128) ((float4*)w2)[t] = p2[t];
        for (int t = tid; t < 256;  t += 128) ((float4*)wl)[t] = pl[t];
    }
    __syncthreads();

    float zv[20];
    const float4* zr = (const float4*)(Zin + (size_t)b * DZF);
#pragma unroll
    for (int t = 0; t < 5; t++) {
        float4 v = zr[t];
        zv[4 * t] = v.x; zv[4 * t + 1] = v.y; zv[4 * t + 2] = v.z; zv[4 * t + 3] = v.w;
    }

    float h1[64], h2[64], o[16];
    dense_reg<20, 64, true >(zv, w0, h1);
    dense_reg<64, 64, true >(h1, w1, h2);
    dense_reg<64, 64, true >(h2, w2, h1);
    dense_reg<64, 16, false>(h1, wl, o);

    float4* dst = (float4*)(g_Zj + (size_t)(j * B_SZ + b) * 16);
#pragma unroll
    for (int t = 0; t < 4; t++)
        dst[t] = make_float4(o[4 * t], o[4 * t + 1], o[4 * t + 2], o[4 * t + 3]);
}

// ============================================================
// Kernel 2: D_j[b][:] = Zj_j[b]·Wu0[48:64] + Z[b]·Wu0[64:84]
// ============================================================
__global__ void __launch_bounds__(256) d_kernel(const float* __restrict__ Zin,
                                                const float* __restrict__ Wu0) {
    __shared__ __align__(16) float w[36 * 128];
    const int j   = blockIdx.y;
    const int tid = threadIdx.x;
    const int b   = blockIdx.x * 256 + tid;

    const float4* src = (const float4*)(Wu0 + 48 * 128);
    for (int t = tid; t < 36 * 32; t += 256) ((float4*)w)[t] = src[t];
    __syncthreads();

    float in[36];
    const float4* zj = (const float4*)(g_Zj + (size_t)(j * B_SZ + b) * 16);
#pragma unroll
    for (int t = 0; t < 4; t++) {
        float4 v = zj[t];
        in[4 * t] = v.x; in[4 * t + 1] = v.y; in[4 * t + 2] = v.z; in[4 * t + 3] = v.w;
    }
    const float4* zr = (const float4*)(Zin + (size_t)b * DZF);
#pragma unroll
    for (int t = 0; t < 5; t++) {
        float4 v = zr[t];
        in[16 + 4 * t] = v.x; in[17 + 4 * t] = v.y; in[18 + 4 * t] = v.z; in[19 + 4 * t] = v.w;
    }

    float* dst = g_D + (size_t)(j * B_SZ + b) * 128;
    u64 acc[32];
#pragma unroll
    for (int half = 0; half < 2; half++) {
        dense_half_reg<36>(in, w + half * 64, acc);
        float4* d4 = (float4*)(dst + half * 64);
#pragma unroll
        for (int q = 0; q < 16; q++) {
            float a, bb, c, d;
            upk2(acc[2 * q], a, bb); upk2(acc[2 * q + 1], c, d);
            d4[q] = make_float4(a, bb, c, d);
        }
    }
}

// ============================================================
// Kernel 3: X-branch + E (unchanged).
// ============================================================
__global__ void __launch_bounds__(256) x_kernel(const float* __restrict__ Xin,
                                                const float* __restrict__ Wx0,
                                                const float* __restrict__ Wx,
                                                const float* __restrict__ Wlx,
                                                const float* __restrict__ Wu0) {
    extern __shared__ float xs[];
    float* w0  = xs;                 // 32*64
    float* w1  = w0 + 2048;          // 64*64
    float* w2  = w1 + 4096;          // 64*64
    float* wl  = w2 + 4096;          // 64*16
    float* wu0 = wl + 1024;          // 48*128
    const int i   = blockIdx.y;
    const int tid = threadIdx.x;

    {
        const float4* p0 = (const float4*)(Wx0 + i * 2048);
        const float4* p1 = (const float4*)(Wx  + i * 8192);
        const float4* p2 = (const float4*)(Wx  + i * 8192 + 4096);
        const float4* pl = (const float4*)(Wlx + 2 * 1024);   // Wlx[DX-1] always (ref bug)
        const float4* pu = (const float4*)Wu0;
        for (int t = tid; t < 512;  t += 256) ((float4*)w0)[t] = p0[t];
        for (int t = tid; t < 1024; t += 256) ((float4*)w1)[t] = p1[t];
        for (int t = tid; t < 1024; t += 256) ((float4*)w2)[t] = p2[t];
        for (int t = tid; t < 256;  t += 256) ((float4*)wl)[t] = pl[t];
        for (int t = tid; t < 1536; t += 256) ((float4*)wu0)[t] = pu[t];
    }
    __syncthreads();

    const int r = blockIdx.x * 256 + tid;
    float in48[48];
    const float4* xr = (const float4*)(Xin + (size_t)r * DXF);
#pragma unroll
    for (int t = 0; t < 8; t++) {
        float4 v = xr[t];
        in48[4 * t] = v.x; in48[4 * t + 1] = v.y; in48[4 * t + 2] = v.z; in48[4 * t + 3] = v.w;
    }

    {
        float xv[32];
#pragma unroll
        for (int t = 0; t < 32; t++) xv[t] = in48[t];
        float h1[64], h2[64], o[16];
        dense_reg<32, 64, true >(xv, w0, h1);
        dense_reg<64, 64, true >(h1, w1, h2);
        dense_reg<64, 64, true >(h2, w2, h1);
        dense_reg<64, 16, false>(h1, wl, o);
#pragma unroll
        for (int t = 0; t < 16; t++) in48[32 + t] = o[t];
    }

    float* ebase = g_E + (size_t)i * 128 * NROWS + r;
    u64 acc[32];
#pragma unroll
    for (int half = 0; half < 2; half++) {
        dense_half_reg<48>(in48, wu0 + half * 64, acc);
        float* eb = ebase + (size_t)(half * 64) * NROWS;
#pragma unroll
        for (int q = 0; q < 32; q++) {
            float lo, hi; upk2(acc[q], lo, hi);
            eb[(size_t)(2 * q) * NROWS]     = lo;
            eb[(size_t)(2 * q + 1) * NROWS] = hi;
        }
    }
}

// ============================================================
// Kernel W-prep: split Wu[layer][k][n] into bf16 hi/lo, transposed
// to [n][k] (col-major B for mma.sync row.col).
// ============================================================
__global__ void __launch_bounds__(256) wprep_kernel(const float* __restrict__ Wu) {
    int idx = blockIdx.x * 256 + threadIdx.x;      // 0..32767
    int ly  = idx >> 14;
    int rem = idx & 16383;
    int k   = rem >> 7;
    int n   = rem & 127;
    float w = Wu[ly * 16384 + k * 128 + n];
    __nv_bfloat16 h = __float2bfloat16_rn(w);
    __nv_bfloat16 l = __float2bfloat16_rn(w - __bfloat162float(h));
    g_Wbf[ly][0][n * 128 + k] = h;
    g_Wbf[ly][1][n * 128 + k] = l;
}

// ============================================================
// Kernel 4: HMMA U-kernel via mma.sync m16n8k16 bf16, split hi/lo.
// Block 256 threads, tile M=128 x N=128, warp owns 16 rows.
// Shared tiles padded to 136 bf16/row (272B) -> conflict-free LDSM.
// ============================================================
#define ASTR_B   272                 // row stride in bytes (136 bf16)
#define SM_AH    0                   // 128*272 = 34816
#define SM_AL    34816
#define SM_WH    69632
#define SM_WL2   104448
#define SM_DSH   139264              // 4*132 floats = 2112 B
#define SM_WLAST 141376              // 128 floats
#define SMEM_UT  141888

__global__ void __launch_bounds__(256) ut_kernel(const float* __restrict__ Wlast) {
    extern __shared__ __align__(16) unsigned char smu[];
    float* Dsh  = (float*)(smu + SM_DSH);
    float* wlsh = (float*)(smu + SM_WLAST);
    const uint32_t sb = smem_u32(smu);

    const int tid  = threadIdx.x;
    const int warp = tid >> 5;
    const int lane = tid & 31;
    const int bx   = blockIdx.x;               // 0..28799
    const int pair = bx / 3200;
    const int tile = bx - pair * 3200;
    const int r0   = tile * 128;
    const int i    = pair / 3;
    const int j    = pair - 3 * i;
    const int b0   = r0 / NPROD;

    // ---- stage D rows + wlast + layer-0 weights ----
    for (int t = tid; t < 512; t += 256) {
        int bl = t >> 7, k = t & 127;
        int bb = b0 + bl;
        if (bb < B_SZ) Dsh[bl * 132 + k] = g_D[((size_t)j * B_SZ + bb) * 128 + k];
    }
    if (tid < 128) wlsh[tid] = Wlast[tid];
    for (int t = tid; t < 4096; t += 256) {     // 2 halves x 128 rows x 16 uint4
        int half = t >> 11, rem = t & 2047, row = rem >> 4, q = rem & 15;
        uint4 v = ((const uint4*)g_Wbf[0][half])[rem];
        *(uint4*)(smu + (half ? SM_WL2 : SM_WH) + row * ASTR_B + q * 16) = v;
    }

    // ---- prologue: A = split(elu(E + D)) into Ah/Al ----
    {
        const float* Ep = g_E + (size_t)i * 128 * NROWS + r0;
        for (int t = tid; t < 4096; t += 256) {
            int k = t >> 5, rg = (t & 31) * 4;
            float4 e = *(const float4*)(Ep + (size_t)k * NROWS + rg);
            float v4[4] = {e.x, e.y, e.z, e.w};
#pragma unroll
            for (int x = 0; x < 4; x++) {
                int row  = rg + x;
                int bidx = (r0 + row) / NPROD - b0;
                float val = eluf(v4[x] + Dsh[bidx * 132 + k]);
                __nv_bfloat16 h = __float2bfloat16_rn(val);
                __nv_bfloat16 l = __float2bfloat16_rn(val - __bfloat162float(h));
                *(__nv_bfloat16*)(smu + SM_AH + row * ASTR_B + k * 2) = h;
                *(__nv_bfloat16*)(smu + SM_AL + row * ASTR_B + k * 2) = l;
            }
        }
    }
    __syncthreads();

    // ldmatrix address bases (bytes)
    const uint32_t aoff = (uint32_t)((warp * 16 + (lane & 15)) * ASTR_B + (lane >> 4) * 16);
    const uint32_t boff = (uint32_t)((((lane & 7) + (lane >> 4) * 8) * ASTR_B) + ((lane >> 3) & 1) * 16);

    const int m0    = warp * 16 + (lane >> 2);
    const int cbase = (lane & 3) * 2;

    float acc[16][4];

#pragma unroll 1
    for (int layer = 0; layer < 2; layer++) {
#pragma unroll
        for (int nb = 0; nb < 16; nb++) {
            acc[nb][0] = 0.f; acc[nb][1] = 0.f; acc[nb][2] = 0.f; acc[nb][3] = 0.f;
        }

#pragma unroll 1
        for (int pass = 0; pass < 3; pass++) {
            const uint32_t aBase = sb + (pass == 2 ? SM_AL : SM_AH) + aoff;
            const uint32_t wBase = sb + (pass == 1 ? SM_WL2 : SM_WH) + boff;
#pragma unroll 2
            for (int kb = 0; kb < 8; kb++) {
                uint32_t a0, a1, a2, a3;
                LDSM4(a0, a1, a2, a3, aBase + kb * 32);
#pragma unroll
                for (int nbp = 0; nbp < 8; nbp++) {
                    uint32_t b0, b1, b2, b3;
                    LDSM4(b0, b1, b2, b3, wBase + nbp * (16 * ASTR_B) + kb * 32);
                    MMA_BF16(acc[2 * nbp],     a0, a1, a2, a3, b0, b1);
                    MMA_BF16(acc[2 * nbp + 1], a0, a1, a2, a3, b2, b3);
                }
            }
        }

        if (layer == 0) {
            // write act2 = split(elu(acc)) back into A tiles (warp-private rows)
#pragma unroll
            for (int nb = 0; nb < 16; nb++) {
                int col = nb * 8 + cbase;
                uint32_t h, l;
                split2(eluf(acc[nb][0]), eluf(acc[nb][1]), h, l);
                *(uint32_t*)(smu + SM_AH + m0 * ASTR_B + col * 2) = h;
                *(uint32_t*)(smu + SM_AL + m0 * ASTR_B + col * 2) = l;
                split2(eluf(acc[nb][2]), eluf(acc[nb][3]), h, l);
                *(uint32_t*)(smu + SM_AH + (m0 + 8) * ASTR_B + col * 2) = h;
                *(uint32_t*)(smu + SM_AL + (m0 + 8) * ASTR_B + col * 2) = l;
            }
            __syncthreads();   // all warps done reading layer-0 W
            for (int t = tid; t < 4096; t += 256) {
                int half = t >> 11, rem = t & 2047, row = rem >> 4, q = rem & 15;
                uint4 v = ((const uint4*)g_Wbf[1][half])[rem];
                *(uint4*)(smu + (half ? SM_WL2 : SM_WH) + row * ASTR_B + q * 16) = v;
            }
            __syncthreads();
        }
    }

    // ---- epilogue: score = sum_c elu(out[m][c]) * wlast[c] ----
    {
        float s0 = 0.f, s1 = 0.f;
#pragma unroll
        for (int nb = 0; nb < 16; nb++) {
            int col = nb * 8 + cbase;
            s0 += eluf(acc[nb][0]) * wlsh[col] + eluf(acc[nb][1]) * wlsh[col + 1];
            s1 += eluf(acc[nb][2]) * wlsh[col] + eluf(acc[nb][3]) * wlsh[col + 1];
        }
        s0 += __shfl_xor_sync(0xFFFFFFFFu, s0, 1);
        s0 += __shfl_xor_sync(0xFFFFFFFFu, s0, 2);
        s1 += __shfl_xor_sync(0xFFFFFFFFu, s1, 1);
        s1 += __shfl_xor_sync(0xFFFFFFFFu, s1, 2);
        if ((lane & 3) == 0) {
            g_scores[(size_t)pair * NROWS + r0 + m0]     = s0;
            g_scores[(size_t)pair * NROWS + r0 + m0 + 8] = s1;
        }
    }
}

// ============================================================
// Kernel 5: softmax over n per (pair, b), accumulate & average.
// ============================================================
__global__ void __launch_bounds__(64) smax_kernel(float* __restrict__ out) {
    __shared__ float red[64];
    const int b   = blockIdx.x;
    const int tid = threadIdx.x;
    const bool act = tid < NPROD;
    float accv = 0.f;

    for (int pair = 0; pair < 9; pair++) {
        float s = act ? g_scores[(size_t)(pair * B_SZ + b) * NPROD + tid] : -1e30f;
        red[tid] = s;
        __syncthreads();
#pragma unroll
        for (int st = 32; st > 0; st >>= 1) {
            if (tid < st) red[tid] = fmaxf(red[tid], red[tid + st]);
            __syncthreads();
        }
        float mx = red[0];
        __syncthreads();
        float e = act ? expf(s - mx) : 0.f;
        red[tid] = e;
        __syncthreads();
#pragma unroll
        for (int st = 32; st > 0; st >>= 1) {
            if (tid < st) red[tid] += red[tid + st];
            __syncthreads();
        }
        float sum = red[0];
        __syncthreads();
        accv += 1e-6f + e / sum;
    }
    if (act)
        out[(size_t)b * NPROD + tid] = accv * (1.f / (1.f + 1e-6f * (float)NPROD)) / 9.f;
}

// ============================================================
extern "C" void kernel_launch(void* const* d_in, const int* in_sizes, int n_in,
                              void* d_out, int out_size) {
    const float* X     = (const float*)d_in[0];
    const float* Z     = (const float*)d_in[1];
    const float* Wx0   = (const float*)d_in[2];
    const float* Wx    = (const float*)d_in[3];
    const float* Wlx   = (const float*)d_in[4];
    const float* Wz0   = (const float*)d_in[5];
    const float* Wz    = (const float*)d_in[6];
    const float* Wlz   = (const float*)d_in[7];
    const float* Wu0   = (const float*)d_in[8];
    const float* Wu    = (const float*)d_in[9];
    const float* Wlast = (const float*)d_in[10];
    float* out = (float*)d_out;

    const size_t smemX = (size_t)(2048 + 4096 + 4096 + 1024 + 6144) * sizeof(float); // 69632
    cudaFuncSetAttribute(x_kernel,  cudaFuncAttributeMaxDynamicSharedMemorySize, (int)smemX);
    cudaFuncSetAttribute(ut_kernel, cudaFuncAttributeMaxDynamicSharedMemorySize, SMEM_UT);

    z_kernel<<<192, 128>>>(Z, Wz0, Wz, Wlz);
    d_kernel<<<dim3(32, 3), 256>>>(Z, Wu0);
    wprep_kernel<<<128, 256>>>(Wu);
    x_kernel<<<dim3(1600, 3), 256, smemX>>>(X, Wx0, Wx, Wlx, Wu0);
    ut_kernel<<<28800, 256, SMEM_UT>>>(Wlast);
    smax_kernel<<<8192, 64>>>(out);
}